// round 10
// baseline (speedup 1.0000x reference)
#include <cuda_runtime.h>
#include <cuda_fp16.h>
#include <cstdint>

// Problem constants (fixed by setup_inputs)
#define BS_TOT 2048      // B*S
#define E_DIM  768
#define E4     192       // E/4
#define K_NB   36
#define H_NUM  4
#define CATD   (H_NUM * E_DIM)   // 3072
#define NSPLIT 4                 // split-K factor for GEMM2

// ---------------- scratch (device globals; no allocations) ----------------
__device__ float g_u[H_NUM * E_DIM];                    // gamma ⊙ (W1 @ W2y)

// fp16 buffers for HMMA GEMMs
__device__ __half g_a[(long)H_NUM * BS_TOT * E_DIM];     // attention out per head
__device__ __half g_w1t[(long)H_NUM * E_DIM * E_DIM];    // W1^T per head
__device__ __half g_cat[(long)BS_TOT * CATD];            // concat head outputs
__device__ __half g_wmt[(long)E_DIM * CATD];             // Wm^T
__device__ float  g_part[(long)NSPLIT * BS_TOT * E_DIM]; // split-K partials (25 MB)

__device__ __forceinline__ float gelu_tanh(float v) {
    const float c = 0.7978845608028654f;   // sqrt(2/pi)
    float t = tanhf(c * (v + 0.044715f * v * v * v));
    return 0.5f * v * (1.0f + t);
}

__device__ __forceinline__ uint32_t smem_u32(const void* p) {
    uint32_t a;
    asm("{ .reg .u64 t; cvta.to.shared.u64 t, %1; cvt.u32.u64 %0, t; }" : "=r"(a) : "l"(p));
    return a;
}

#define CP_ASYNC16(sm, gm) \
    asm volatile("cp.async.cg.shared.global [%0], [%1], 16;" :: "r"(sm), "l"(gm))
#define CP_COMMIT() asm volatile("cp.async.commit_group;" ::: "memory")
#define CP_WAIT(n)  asm volatile("cp.async.wait_group %0;" :: "n"(n) : "memory")

#define LDSM_X4(r0, r1, r2, r3, a) \
    asm volatile("ldmatrix.sync.aligned.m8n8.x4.shared.b16 {%0,%1,%2,%3}, [%4];" \
                 : "=r"(r0), "=r"(r1), "=r"(r2), "=r"(r3) : "r"(a))

#define MMA16816(d, a, b0v, b1v) \
    asm volatile("mma.sync.aligned.m16n8k16.row.col.f32.f16.f16.f32 " \
                 "{%0,%1,%2,%3}, {%4,%5,%6,%7}, {%8,%9}, {%0,%1,%2,%3};" \
                 : "+f"((d)[0]), "+f"((d)[1]), "+f"((d)[2]), "+f"((d)[3]) \
                 : "r"((a)[0]), "r"((a)[1]), "r"((a)[2]), "r"((a)[3]), \
                   "r"(b0v), "r"(b1v))

// ---------------- combined prep: transposes (W1, Wm) + prep_u in one launch ----
__global__ __launch_bounds__(256) void prep_all(const float* __restrict__ W1,
                                                const float* __restrict__ Wm,
                                                const float* __restrict__ W2y,
                                                const float* __restrict__ gamma,
                                                __half* __restrict__ w1t,
                                                __half* __restrict__ wmt) {
    int b = blockIdx.x;
    if (b < 4608) {
        const float* in;
        __half* oh;
        int K, N, k0, n0;
        if (b < 2304) {
            int z = b / 576, r = b % 576;
            in = W1 + (long)z * E_DIM * E_DIM;
            oh = w1t + (long)z * E_DIM * E_DIM;
            K = 768; N = 768;
            k0 = (r % 24) * 32; n0 = (r / 24) * 32;
        } else {
            int r = b - 2304;
            in = Wm; oh = wmt;
            K = 3072; N = 768;
            k0 = (r % 96) * 32; n0 = (r / 96) * 32;
        }
        __shared__ float t[32][33];
        int tx = threadIdx.x & 31, ty = threadIdx.x >> 5;
        for (int i = ty; i < 32; i += 8)
            t[i][tx] = in[(long)(k0 + i) * N + n0 + tx];
        __syncthreads();
        for (int i = ty; i < 32; i += 8)
            oh[(long)(n0 + i) * K + k0 + tx] = __float2half(t[tx][i]);
    } else {
        int warp = (b - 4608) * 8 + (threadIdx.x >> 5);
        int lane = threadIdx.x & 31;
        if (warp >= H_NUM * E_DIM) return;
        int h = warp / E_DIM;
        const float* wrow = W1 + (long)warp * E_DIM;
        const float* w2 = W2y + h * E_DIM;
        float s = 0.f;
        #pragma unroll 4
        for (int j = lane; j < E_DIM; j += 32) s += wrow[j] * w2[j];
        #pragma unroll
        for (int o = 16; o; o >>= 1) s += __shfl_xor_sync(0xffffffffu, s, o);
        if (lane == 0) g_u[warp] = gamma[warp] * s;
    }
}

// ---------------- fused y kernel: one CTA per token n (256 threads, occ 4) -----
__global__ __launch_bounds__(256, 4) void fused_y(const float* __restrict__ y,
                                                  const float* __restrict__ gamma,
                                                  const float* __restrict__ beta) {
    __shared__ float4 u_s[H_NUM * E4];     // 12 KB
    __shared__ float yd_s[K_NB * 4];
    __shared__ float mu_s[K_NB];
    __shared__ float rs_s[K_NB];
    __shared__ float w_s[H_NUM * K_NB];
    __shared__ float csub[H_NUM];

    const int n = blockIdx.x;
    const int tid = threadIdx.x;
    const int w = tid >> 5, lane = tid & 31;

    const float4* u4 = (const float4*)g_u;
    for (int i = tid; i < H_NUM * E4; i += 256) u_s[i] = u4[i];
    __syncthreads();

    const float4* yb = (const float4*)y + (long)n * K_NB * E4;

    // ---- phase 1: 8 warps, rows w, w+8, ... with next-row prefetch ----
    float4 v[6];
    {
        const float4* yr = yb + (long)w * E4;
        #pragma unroll
        for (int j = 0; j < 6; j++) v[j] = yr[lane + 32 * j];
    }
    for (int k = w; k < K_NB; k += 8) {
        float4 vn[6];
        const int kn = k + 8;
        if (kn < K_NB) {
            const float4* yr2 = yb + (long)kn * E4;
            #pragma unroll
            for (int j = 0; j < 6; j++) vn[j] = yr2[lane + 32 * j];
        }

        float s = 0.f, sq = 0.f;
        #pragma unroll
        for (int j = 0; j < 6; j++) {
            s  += v[j].x + v[j].y + v[j].z + v[j].w;
            sq += v[j].x * v[j].x + v[j].y * v[j].y + v[j].z * v[j].z + v[j].w * v[j].w;
        }
        #pragma unroll
        for (int o = 16; o; o >>= 1) {
            s  += __shfl_xor_sync(0xffffffffu, s, o);
            sq += __shfl_xor_sync(0xffffffffu, sq, o);
        }
        const float inv = 1.0f / 768.0f;
        float mean = s * inv;
        float var  = sq * inv - mean * mean;
        float rstd = rsqrtf(var + 1e-5f);

        float p0 = 0.f, p1 = 0.f, p2 = 0.f, p3 = 0.f;
        #pragma unroll
        for (int j = 0; j < 6; j++) {
            int idx = lane + 32 * j;
            float tx = v[j].x - mean, ty = v[j].y - mean, tz = v[j].z - mean, tw = v[j].w - mean;
            float4 u0 = u_s[idx];
            float4 u1 = u_s[E4 + idx];
            float4 u2 = u_s[2 * E4 + idx];
            float4 u3 = u_s[3 * E4 + idx];
            p0 += tx * u0.x + ty * u0.y + tz * u0.z + tw * u0.w;
            p1 += tx * u1.x + ty * u1.y + tz * u1.z + tw * u1.w;
            p2 += tx * u2.x + ty * u2.y + tz * u2.z + tw * u2.w;
            p3 += tx * u3.x + ty * u3.y + tz * u3.z + tw * u3.w;
        }
        #pragma unroll
        for (int o = 16; o; o >>= 1) {
            p0 += __shfl_xor_sync(0xffffffffu, p0, o);
            p1 += __shfl_xor_sync(0xffffffffu, p1, o);
            p2 += __shfl_xor_sync(0xffffffffu, p2, o);
            p3 += __shfl_xor_sync(0xffffffffu, p3, o);
        }
        if (lane == 0) {
            mu_s[k] = mean;
            rs_s[k] = rstd;
            yd_s[k * 4 + 0] = p0 * rstd;
            yd_s[k * 4 + 1] = p1 * rstd;
            yd_s[k * 4 + 2] = p2 * rstd;
            yd_s[k * 4 + 3] = p3 * rstd;
        }
        #pragma unroll
        for (int j = 0; j < 6; j++) v[j] = vn[j];
    }
    __syncthreads();

    // ---- phase 2: softmax per head (warps 0..3) ----
    if (w < H_NUM) {
        int h = w;
        float l1 = (lane < K_NB) ? yd_s[lane * 4 + h] : -1e30f;
        float l2 = (lane < K_NB - 32) ? yd_s[(lane + 32) * 4 + h] : -1e30f;
        float m = fmaxf(l1, l2);
        #pragma unroll
        for (int o = 16; o; o >>= 1) m = fmaxf(m, __shfl_xor_sync(0xffffffffu, m, o));
        float e1 = (lane < K_NB) ? expf(l1 - m) : 0.f;
        float e2 = (lane < K_NB - 32) ? expf(l2 - m) : 0.f;
        float se = e1 + e2;
        #pragma unroll
        for (int o = 16; o; o >>= 1) se += __shfl_xor_sync(0xffffffffu, se, o);
        float invs = 1.0f / se;
        float wv1 = 0.f, wv2 = 0.f;
        if (lane < K_NB)      { wv1 = e1 * invs * rs_s[lane];      w_s[h * K_NB + lane]      = wv1; }
        if (lane < K_NB - 32) { wv2 = e2 * invs * rs_s[lane + 32]; w_s[h * K_NB + lane + 32] = wv2; }
        float cp = (lane < K_NB ? wv1 * mu_s[lane] : 0.f) +
                   (lane < K_NB - 32 ? wv2 * mu_s[lane + 32] : 0.f);
        #pragma unroll
        for (int o = 16; o; o >>= 1) cp += __shfl_xor_sync(0xffffffffu, cp, o);
        if (lane == 0) csub[h] = cp;
    }
    __syncthreads();

    // ---- phase 3: weighted sum from L2 (threads 0..191, one float4 col each) ----
    if (tid < E4) {
        float acc[H_NUM][4];
        #pragma unroll
        for (int h = 0; h < H_NUM; h++)
            #pragma unroll
            for (int q = 0; q < 4; q++) acc[h][q] = 0.f;
        #pragma unroll 4
        for (int k = 0; k < K_NB; k++) {
            float4 vv = yb[k * E4 + tid];
            #pragma unroll
            for (int h = 0; h < H_NUM; h++) {
                float wv = w_s[h * K_NB + k];
                acc[h][0] += wv * vv.x; acc[h][1] += wv * vv.y;
                acc[h][2] += wv * vv.z; acc[h][3] += wv * vv.w;
            }
        }
        #pragma unroll
        for (int h = 0; h < H_NUM; h++) {
            float4 ga = ((const float4*)gamma)[h * E4 + tid];
            float4 be = ((const float4*)beta)[h * E4 + tid];
            float c = csub[h];
            float o0 = (acc[h][0] - c) * ga.x + be.x;
            float o1 = (acc[h][1] - c) * ga.y + be.y;
            float o2 = (acc[h][2] - c) * ga.z + be.z;
            float o3 = (acc[h][3] - c) * ga.w + be.w;
            long base = ((long)h * BS_TOT + n) * E_DIM + tid * 4;
            __half2* pa = (__half2*)(g_a + base);
            pa[0] = __floats2half2_rn(o0, o1);
            pa[1] = __floats2half2_rn(o2, o3);
        }
    }
}

// ========== HMMA GEMM: TM=64, TN=64, KC=64, 3-stage, one barrier/iter ==========
// MODE 0: z = head;   cat[m][z*768+n] = half(GELU(x[m][n] + D + bias[n]))
// MODE 2: z = split;  part[z][m][n] = D   (split-K partial, fp32, plain stores)
//
// cp.async group invariant: ONE commit_group per iteration, unconditionally
// (empty groups at the tail) -- wait_group(1) then provably drains chunk c.
#define TMV 64
#define TNV 64
#define KC 64
#define ROWB 144                      // 64 halfs (128B) + 16B pad; stride 36 banks -> conflict-free
#define NSTG 3
#define BUF_A (TMV * ROWB)
#define BUF_B (TNV * ROWB)
#define STAGE (BUF_A + BUF_B)         // 18432 B
#define GEMM_SMEM (NSTG * STAGE)      // 55296 B

template <int MODE>
__global__ __launch_bounds__(256) void gemm_mma(
    const __half* __restrict__ A, long aBatch, int lda,
    const __half* __restrict__ B, long bBatch, int ldb,
    const float* __restrict__ bias, int biasBatch,
    const float* __restrict__ x,
    float* __restrict__ outF, __half* __restrict__ outC,
    int ldc, int colBatch, int K) {
    extern __shared__ char smem[];
    uint32_t sb = smem_u32(smem);
    const int tid = threadIdx.x, w = tid >> 5, l = tid & 31;

    int z = blockIdx.z;
    A += (long)z * aBatch;
    B += (long)z * bBatch;
    bias += (long)z * biasBatch;
    int coloff = 0;
    if (MODE == 0) coloff = z * colBatch;
    if (MODE == 2) outF += (long)z * colBatch;
    const int m0 = blockIdx.y * TMV, n0 = blockIdx.x * TNV;
    const int wm = (w >> 2) * 32, wn = (w & 3) * 16;

    // gmem->smem: 32 rows per pass, 8x16B chunks per row (KC=64 halfs = 128B)
    const int gr = tid >> 3, gc = tid & 7;
    const long aoff0 = ((long)(m0 + gr) * lda + gc * 8) * 2;
    const long aoff1 = aoff0 + (long)32 * lda * 2;
    const long boff0 = ((long)(n0 + gr) * ldb + gc * 8) * 2;
    const long boff1 = boff0 + (long)32 * ldb * 2;
    const uint32_t soff0 = gr * ROWB + gc * 16;
    const uint32_t soff1 = (gr + 32) * ROWB + gc * 16;
    const char* aB = (const char*)A;
    const char* bB = (const char*)B;

    const uint32_t a_r = (l & 15) * ROWB + (l >> 4) * 16;
    const uint32_t b_r = (((l >> 4) & 1) * 8 + (l & 7)) * ROWB + ((l >> 3) & 1) * 16;

    float acc[2][2][4];
    #pragma unroll
    for (int i = 0; i < 2; i++)
        #pragma unroll
        for (int j = 0; j < 2; j++)
            #pragma unroll
            for (int q = 0; q < 4; q++) acc[i][j][q] = 0.f;

    const int NC = K / KC;

    // prologue: chunks 0, 1 (groups g0, g1)
    #pragma unroll
    for (int pc = 0; pc < 2; pc++) {
        uint32_t st = sb + pc * STAGE;
        long kb = (long)pc * KC * 2;
        CP_ASYNC16(st + soff0, aB + aoff0 + kb);
        CP_ASYNC16(st + soff1, aB + aoff1 + kb);
        CP_ASYNC16(st + BUF_A + soff0, bB + boff0 + kb);
        CP_ASYNC16(st + BUF_A + soff1, bB + boff1 + kb);
        CP_COMMIT();
    }

    for (int c = 0; c < NC; c++) {
        // groups committed so far: g0..g_{c+1}; wait_group(1) => chunk c landed
        CP_WAIT(1);
        __syncthreads();

        uint32_t st = sb + (c % NSTG) * STAGE;
        #pragma unroll
        for (int kk = 0; kk < 4; kk++) {
            uint32_t kby = kk * 32;   // 16 halfs = 32B
            uint32_t ah[2][4], bh[4];
            #pragma unroll
            for (int mt = 0; mt < 2; mt++) {
                uint32_t ra = st + (wm + mt * 16) * ROWB + a_r + kby;
                LDSM_X4(ah[mt][0], ah[mt][1], ah[mt][2], ah[mt][3], ra);
            }
            {
                uint32_t rb = st + BUF_A + wn * ROWB + b_r + kby;
                LDSM_X4(bh[0], bh[1], bh[2], bh[3], rb);
            }
            #pragma unroll
            for (int mt = 0; mt < 2; mt++) {
                #pragma unroll
                for (int nt = 0; nt < 2; nt++) {
                    MMA16816(acc[mt][nt], ah[mt], bh[nt * 2], bh[nt * 2 + 1]);
                }
            }
        }

        // prefetch chunk c+2 into stage (c+2)%3 (free past this iter's barrier);
        // commit UNCONDITIONALLY to keep group accounting at the tail.
        if (c + 2 < NC) {
            uint32_t sn = sb + ((c + 2) % NSTG) * STAGE;
            long kb = (long)(c + 2) * KC * 2;
            CP_ASYNC16(sn + soff0, aB + aoff0 + kb);
            CP_ASYNC16(sn + soff1, aB + aoff1 + kb);
            CP_ASYNC16(sn + BUF_A + soff0, bB + boff0 + kb);
            CP_ASYNC16(sn + BUF_A + soff1, bB + boff1 + kb);
        }
        CP_COMMIT();
    }

    // epilogue
    #pragma unroll
    for (int mt = 0; mt < 2; mt++) {
        #pragma unroll
        for (int nt = 0; nt < 2; nt++) {
            int row0 = m0 + wm + mt * 16 + (l >> 2);
            int col = n0 + wn + nt * 8 + ((l & 3) << 1);
            #pragma unroll
            for (int rh = 0; rh < 2; rh++) {
                int row = row0 + rh * 8;
                float d0 = acc[mt][nt][rh * 2 + 0];
                float d1 = acc[mt][nt][rh * 2 + 1];
                if (MODE == 0) {
                    float2 xv = *(const float2*)(x + (long)row * E_DIM + col);
                    float2 bv = *(const float2*)(bias + col);
                    float o0 = gelu_tanh(xv.x + d0 + bv.x);
                    float o1 = gelu_tanh(xv.y + d1 + bv.y);
                    *(__half2*)(outC + (long)row * ldc + coloff + col) =
                        __floats2half2_rn(o0, o1);
                } else {
                    float2 o;
                    o.x = d0; o.y = d1;
                    *(float2*)(outF + (long)row * ldc + col) = o;
                }
            }
        }
    }
}

// ---------------- reduce: out = x + GELU(sum_s part[s] + bm) ----------------
__global__ __launch_bounds__(256) void reduce_out(const float* __restrict__ part,
                                                  const float* __restrict__ x,
                                                  const float* __restrict__ bm,
                                                  float* __restrict__ out) {
    const long QT = (long)BS_TOT * E4;     // total float4 elements
    long i = (long)blockIdx.x * 256 + threadIdx.x;
    if (i >= QT) return;
    int colq = (int)(i % E4);
    const float4* p4 = (const float4*)part;
    float4 s = p4[i];
    #pragma unroll
    for (int sp = 1; sp < NSPLIT; sp++) {
        float4 t = p4[sp * QT + i];
        s.x += t.x; s.y += t.y; s.z += t.z; s.w += t.w;
    }
    float4 bv = ((const float4*)bm)[colq];
    float4 xv = ((const float4*)x)[i];
    float4 o;
    o.x = xv.x + gelu_tanh(s.x + bv.x);
    o.y = xv.y + gelu_tanh(s.y + bv.y);
    o.z = xv.z + gelu_tanh(s.z + bv.z);
    o.w = xv.w + gelu_tanh(s.w + bv.w);
    ((float4*)out)[i] = o;
}

// ---------------- launch ----------------
extern "C" void kernel_launch(void* const* d_in, const int* in_sizes, int n_in,
                              void* d_out, int out_size) {
    (void)in_sizes; (void)n_in; (void)out_size;
    const float* x     = (const float*)d_in[0];   // [2048,768]
    const float* y     = (const float*)d_in[1];   // [2048,36,768]
    const float* gamma = (const float*)d_in[2];   // [4,768]
    const float* beta  = (const float*)d_in[3];   // [4,768]
    const float* W1    = (const float*)d_in[4];   // [4,768,768]
    const float* b1    = (const float*)d_in[5];   // [4,768]
    // d_in[6] = W2x, d_in[8] = b2: cancel in the softmax — unused.
    const float* W2y   = (const float*)d_in[7];   // [4,768]
    const float* Wm    = (const float*)d_in[9];   // [3072,768]
    const float* bm    = (const float*)d_in[10];  // [768]
    float* out = (float*)d_out;

    __half *p_a, *p_w1t, *p_cat, *p_wmt;
    float* p_part;
    cudaGetSymbolAddress((void**)&p_a, g_a);
    cudaGetSymbolAddress((void**)&p_w1t, g_w1t);
    cudaGetSymbolAddress((void**)&p_cat, g_cat);
    cudaGetSymbolAddress((void**)&p_wmt, g_wmt);
    cudaGetSymbolAddress((void**)&p_part, g_part);

    cudaFuncSetAttribute(gemm_mma<0>, cudaFuncAttributeMaxDynamicSharedMemorySize, GEMM_SMEM);
    cudaFuncSetAttribute(gemm_mma<2>, cudaFuncAttributeMaxDynamicSharedMemorySize, GEMM_SMEM);

    prep_all<<<4992, 256>>>(W1, Wm, W2y, gamma, p_w1t, p_wmt);
    fused_y<<<BS_TOT, 256>>>(y, gamma, beta);

    // GEMM1 (per head): cat[:, h*768+n] = GELU(x + A_h @ W1[h]^T + b1[h])
    gemm_mma<0><<<dim3(E_DIM / TNV, BS_TOT / TMV, H_NUM), 256, GEMM_SMEM>>>(
        p_a, (long)BS_TOT * E_DIM, E_DIM,
        p_w1t, (long)E_DIM * E_DIM, E_DIM,
        b1, E_DIM, x,
        nullptr, p_cat, CATD, E_DIM, E_DIM);
    // GEMM2 split-K: part[s] = cat[:, s*768:(s+1)*768] @ WmT[:, s*768:(s+1)*768]^T
    gemm_mma<2><<<dim3(E_DIM / TNV, BS_TOT / TMV, NSPLIT), 256, GEMM_SMEM>>>(
        p_cat, 768, CATD,
        p_wmt, 768, CATD,
        bm, 0, nullptr,
        p_part, nullptr, E_DIM, BS_TOT * E_DIM, CATD / NSPLIT);
    // reduce: out = x + GELU(sum parts + bm)
    reduce_out<<<(BS_TOT * E4 + 255) / 256, 256>>>(p_part, x, bm, out);
}

// round 11
// speedup vs baseline: 1.0823x; 1.0823x over previous
#include <cuda_runtime.h>
#include <cuda_fp16.h>
#include <cstdint>

// Problem constants (fixed by setup_inputs)
#define BS_TOT 2048      // B*S
#define E_DIM  768
#define E4     192       // E/4
#define K_NB   36
#define H_NUM  4
#define CATD   (H_NUM * E_DIM)   // 3072
#define NSPLIT 4                 // split-K factor for GEMM2

// ---------------- scratch (device globals; no allocations) ----------------
__device__ float g_u[H_NUM * E_DIM];                    // gamma ⊙ (W1 @ W2y)

// fp16 buffers for HMMA GEMMs
__device__ __half g_a[(long)H_NUM * BS_TOT * E_DIM];     // attention out per head
__device__ __half g_w1t[(long)H_NUM * E_DIM * E_DIM];    // W1^T per head
__device__ __half g_cat[(long)BS_TOT * CATD];            // concat head outputs
__device__ __half g_wmt[(long)E_DIM * CATD];             // Wm^T
__device__ float  g_part[(long)NSPLIT * BS_TOT * E_DIM]; // split-K partials (25 MB)

__device__ __forceinline__ float gelu_tanh(float v) {
    const float c = 0.7978845608028654f;   // sqrt(2/pi)
    float t = tanhf(c * (v + 0.044715f * v * v * v));
    return 0.5f * v * (1.0f + t);
}

__device__ __forceinline__ uint32_t smem_u32(const void* p) {
    uint32_t a;
    asm("{ .reg .u64 t; cvta.to.shared.u64 t, %1; cvt.u32.u64 %0, t; }" : "=r"(a) : "l"(p));
    return a;
}

#define CP_ASYNC16(sm, gm) \
    asm volatile("cp.async.cg.shared.global [%0], [%1], 16;" :: "r"(sm), "l"(gm))
#define CP_COMMIT() asm volatile("cp.async.commit_group;" ::: "memory")
#define CP_WAIT(n)  asm volatile("cp.async.wait_group %0;" :: "n"(n) : "memory")

#define LDSM_X4(r0, r1, r2, r3, a) \
    asm volatile("ldmatrix.sync.aligned.m8n8.x4.shared.b16 {%0,%1,%2,%3}, [%4];" \
                 : "=r"(r0), "=r"(r1), "=r"(r2), "=r"(r3) : "r"(a))

#define MMA16816(d, a, b0v, b1v) \
    asm volatile("mma.sync.aligned.m16n8k16.row.col.f32.f16.f16.f32 " \
                 "{%0,%1,%2,%3}, {%4,%5,%6,%7}, {%8,%9}, {%0,%1,%2,%3};" \
                 : "+f"((d)[0]), "+f"((d)[1]), "+f"((d)[2]), "+f"((d)[3]) \
                 : "r"((a)[0]), "r"((a)[1]), "r"((a)[2]), "r"((a)[3]), \
                   "r"(b0v), "r"(b1v))

// ---------------- combined prep: transposes (W1, Wm) + prep_u in one launch ----
__global__ __launch_bounds__(256) void prep_all(const float* __restrict__ W1,
                                                const float* __restrict__ Wm,
                                                const float* __restrict__ W2y,
                                                const float* __restrict__ gamma,
                                                __half* __restrict__ w1t,
                                                __half* __restrict__ wmt) {
    int b = blockIdx.x;
    if (b < 4608) {
        const float* in;
        __half* oh;
        int K, N, k0, n0;
        if (b < 2304) {
            int z = b / 576, r = b % 576;
            in = W1 + (long)z * E_DIM * E_DIM;
            oh = w1t + (long)z * E_DIM * E_DIM;
            K = 768; N = 768;
            k0 = (r % 24) * 32; n0 = (r / 24) * 32;
        } else {
            int r = b - 2304;
            in = Wm; oh = wmt;
            K = 3072; N = 768;
            k0 = (r % 96) * 32; n0 = (r / 96) * 32;
        }
        __shared__ float t[32][33];
        int tx = threadIdx.x & 31, ty = threadIdx.x >> 5;
        for (int i = ty; i < 32; i += 8)
            t[i][tx] = in[(long)(k0 + i) * N + n0 + tx];
        __syncthreads();
        for (int i = ty; i < 32; i += 8)
            oh[(long)(n0 + i) * K + k0 + tx] = __float2half(t[tx][i]);
    } else {
        int warp = (b - 4608) * 8 + (threadIdx.x >> 5);
        int lane = threadIdx.x & 31;
        if (warp >= H_NUM * E_DIM) return;
        int h = warp / E_DIM;
        const float* wrow = W1 + (long)warp * E_DIM;
        const float* w2 = W2y + h * E_DIM;
        float s = 0.f;
        #pragma unroll 4
        for (int j = lane; j < E_DIM; j += 32) s += wrow[j] * w2[j];
        #pragma unroll
        for (int o = 16; o; o >>= 1) s += __shfl_xor_sync(0xffffffffu, s, o);
        if (lane == 0) g_u[warp] = gamma[warp] * s;
    }
}

// ---------------- fused y kernel: one CTA per token n (256 threads, occ 4) -----
__global__ __launch_bounds__(256, 4) void fused_y(const float* __restrict__ y,
                                                  const float* __restrict__ gamma,
                                                  const float* __restrict__ beta) {
    __shared__ float4 u_s[H_NUM * E4];     // 12 KB
    __shared__ float yd_s[K_NB * 4];
    __shared__ float mu_s[K_NB];
    __shared__ float rs_s[K_NB];
    __shared__ float w_s[H_NUM * K_NB];
    __shared__ float csub[H_NUM];

    const int n = blockIdx.x;
    const int tid = threadIdx.x;
    const int w = tid >> 5, lane = tid & 31;

    const float4* u4 = (const float4*)g_u;
    for (int i = tid; i < H_NUM * E4; i += 256) u_s[i] = u4[i];
    __syncthreads();

    const float4* yb = (const float4*)y + (long)n * K_NB * E4;

    // ---- phase 1: 8 warps, rows w, w+8, ... with next-row prefetch ----
    float4 v[6];
    {
        const float4* yr = yb + (long)w * E4;
        #pragma unroll
        for (int j = 0; j < 6; j++) v[j] = yr[lane + 32 * j];
    }
    for (int k = w; k < K_NB; k += 8) {
        float4 vn[6];
        const int kn = k + 8;
        if (kn < K_NB) {
            const float4* yr2 = yb + (long)kn * E4;
            #pragma unroll
            for (int j = 0; j < 6; j++) vn[j] = yr2[lane + 32 * j];
        }

        float s = 0.f, sq = 0.f;
        #pragma unroll
        for (int j = 0; j < 6; j++) {
            s  += v[j].x + v[j].y + v[j].z + v[j].w;
            sq += v[j].x * v[j].x + v[j].y * v[j].y + v[j].z * v[j].z + v[j].w * v[j].w;
        }
        #pragma unroll
        for (int o = 16; o; o >>= 1) {
            s  += __shfl_xor_sync(0xffffffffu, s, o);
            sq += __shfl_xor_sync(0xffffffffu, sq, o);
        }
        const float inv = 1.0f / 768.0f;
        float mean = s * inv;
        float var  = sq * inv - mean * mean;
        float rstd = rsqrtf(var + 1e-5f);

        float p0 = 0.f, p1 = 0.f, p2 = 0.f, p3 = 0.f;
        #pragma unroll
        for (int j = 0; j < 6; j++) {
            int idx = lane + 32 * j;
            float tx = v[j].x - mean, ty = v[j].y - mean, tz = v[j].z - mean, tw = v[j].w - mean;
            float4 u0 = u_s[idx];
            float4 u1 = u_s[E4 + idx];
            float4 u2 = u_s[2 * E4 + idx];
            float4 u3 = u_s[3 * E4 + idx];
            p0 += tx * u0.x + ty * u0.y + tz * u0.z + tw * u0.w;
            p1 += tx * u1.x + ty * u1.y + tz * u1.z + tw * u1.w;
            p2 += tx * u2.x + ty * u2.y + tz * u2.z + tw * u2.w;
            p3 += tx * u3.x + ty * u3.y + tz * u3.z + tw * u3.w;
        }
        #pragma unroll
        for (int o = 16; o; o >>= 1) {
            p0 += __shfl_xor_sync(0xffffffffu, p0, o);
            p1 += __shfl_xor_sync(0xffffffffu, p1, o);
            p2 += __shfl_xor_sync(0xffffffffu, p2, o);
            p3 += __shfl_xor_sync(0xffffffffu, p3, o);
        }
        if (lane == 0) {
            mu_s[k] = mean;
            rs_s[k] = rstd;
            yd_s[k * 4 + 0] = p0 * rstd;
            yd_s[k * 4 + 1] = p1 * rstd;
            yd_s[k * 4 + 2] = p2 * rstd;
            yd_s[k * 4 + 3] = p3 * rstd;
        }
        #pragma unroll
        for (int j = 0; j < 6; j++) v[j] = vn[j];
    }
    __syncthreads();

    // ---- phase 2: softmax per head (warps 0..3) ----
    if (w < H_NUM) {
        int h = w;
        float l1 = (lane < K_NB) ? yd_s[lane * 4 + h] : -1e30f;
        float l2 = (lane < K_NB - 32) ? yd_s[(lane + 32) * 4 + h] : -1e30f;
        float m = fmaxf(l1, l2);
        #pragma unroll
        for (int o = 16; o; o >>= 1) m = fmaxf(m, __shfl_xor_sync(0xffffffffu, m, o));
        float e1 = (lane < K_NB) ? expf(l1 - m) : 0.f;
        float e2 = (lane < K_NB - 32) ? expf(l2 - m) : 0.f;
        float se = e1 + e2;
        #pragma unroll
        for (int o = 16; o; o >>= 1) se += __shfl_xor_sync(0xffffffffu, se, o);
        float invs = 1.0f / se;
        float wv1 = 0.f, wv2 = 0.f;
        if (lane < K_NB)      { wv1 = e1 * invs * rs_s[lane];      w_s[h * K_NB + lane]      = wv1; }
        if (lane < K_NB - 32) { wv2 = e2 * invs * rs_s[lane + 32]; w_s[h * K_NB + lane + 32] = wv2; }
        float cp = (lane < K_NB ? wv1 * mu_s[lane] : 0.f) +
                   (lane < K_NB - 32 ? wv2 * mu_s[lane + 32] : 0.f);
        #pragma unroll
        for (int o = 16; o; o >>= 1) cp += __shfl_xor_sync(0xffffffffu, cp, o);
        if (lane == 0) csub[h] = cp;
    }
    __syncthreads();

    // ---- phase 3: weighted sum from L2 (threads 0..191, one float4 col each) ----
    if (tid < E4) {
        float acc[H_NUM][4];
        #pragma unroll
        for (int h = 0; h < H_NUM; h++)
            #pragma unroll
            for (int q = 0; q < 4; q++) acc[h][q] = 0.f;
        #pragma unroll 4
        for (int k = 0; k < K_NB; k++) {
            float4 vv = yb[k * E4 + tid];
            #pragma unroll
            for (int h = 0; h < H_NUM; h++) {
                float wv = w_s[h * K_NB + k];
                acc[h][0] += wv * vv.x; acc[h][1] += wv * vv.y;
                acc[h][2] += wv * vv.z; acc[h][3] += wv * vv.w;
            }
        }
        #pragma unroll
        for (int h = 0; h < H_NUM; h++) {
            float4 ga = ((const float4*)gamma)[h * E4 + tid];
            float4 be = ((const float4*)beta)[h * E4 + tid];
            float c = csub[h];
            float o0 = (acc[h][0] - c) * ga.x + be.x;
            float o1 = (acc[h][1] - c) * ga.y + be.y;
            float o2 = (acc[h][2] - c) * ga.z + be.z;
            float o3 = (acc[h][3] - c) * ga.w + be.w;
            long base = ((long)h * BS_TOT + n) * E_DIM + tid * 4;
            __half2* pa = (__half2*)(g_a + base);
            pa[0] = __floats2half2_rn(o0, o1);
            pa[1] = __floats2half2_rn(o2, o3);
        }
    }
}

// ====== HMMA GEMM: 128 thr / 4 warps, 32x32 warp tile, KC=64, 3-stage =========
// CTA tile TM=64 x TN=64. Warp w: rows (w&1)*32, cols (w>>1)*32.
// Per kk-step: 2 A-LDSM + 2 B-LDSM -> 8 MMAs (2:1 MMA:LDSM, 2x fragment reuse).
// MODE 0: z = head;   cat[m][z*768+n] = half(GELU(x[m][n] + D + bias[n]))
// MODE 2: z = split;  part[z][m][n] = D   (split-K partial, fp32, plain stores)
//
// cp.async group invariant: ONE commit_group per iteration, unconditionally
// (empty groups at the tail) -- wait_group(1) then provably drains chunk c.
#define TMV 64
#define TNV 64
#define KC 64
#define ROWB 144                      // 64 halfs (128B) + 16B pad; stride 36 banks -> conflict-free
#define NSTG 3
#define BUF_A (TMV * ROWB)
#define BUF_B (TNV * ROWB)
#define STAGE (BUF_A + BUF_B)         // 18432 B
#define GEMM_SMEM (NSTG * STAGE)      // 55296 B

template <int MODE>
__global__ __launch_bounds__(128) void gemm_mma(
    const __half* __restrict__ A, long aBatch, int lda,
    const __half* __restrict__ B, long bBatch, int ldb,
    const float* __restrict__ bias, int biasBatch,
    const float* __restrict__ x,
    float* __restrict__ outF, __half* __restrict__ outC,
    int ldc, int colBatch, int K) {
    extern __shared__ char smem[];
    uint32_t sb = smem_u32(smem);
    const int tid = threadIdx.x, w = tid >> 5, l = tid & 31;

    int z = blockIdx.z;
    A += (long)z * aBatch;
    B += (long)z * bBatch;
    bias += (long)z * biasBatch;
    int coloff = 0;
    if (MODE == 0) coloff = z * colBatch;
    if (MODE == 2) outF += (long)z * colBatch;
    const int m0 = blockIdx.y * TMV, n0 = blockIdx.x * TNV;
    const int wm = (w & 1) * 32, wn = (w >> 1) * 32;

    // gmem->smem: 128 threads; rows gr+16j (j=0..3), 16B chunk gc, for A and B
    const int gr = tid >> 3, gc = tid & 7;
    long aoff[4], boff[4];
    uint32_t soff[4];
    #pragma unroll
    for (int j = 0; j < 4; j++) {
        aoff[j] = ((long)(m0 + gr + 16 * j) * lda + gc * 8) * 2;
        boff[j] = ((long)(n0 + gr + 16 * j) * ldb + gc * 8) * 2;
        soff[j] = (gr + 16 * j) * ROWB + gc * 16;
    }
    const char* aB = (const char*)A;
    const char* bB = (const char*)B;

    const uint32_t a_r = (l & 15) * ROWB + (l >> 4) * 16;
    const uint32_t b_r = (((l >> 4) & 1) * 8 + (l & 7)) * ROWB + ((l >> 3) & 1) * 16;

    float acc[2][4][4];
    #pragma unroll
    for (int i = 0; i < 2; i++)
        #pragma unroll
        for (int j = 0; j < 4; j++)
            #pragma unroll
            for (int q = 0; q < 4; q++) acc[i][j][q] = 0.f;

    const int NC = K / KC;

    // prologue: chunks 0, 1 (groups g0, g1)
    #pragma unroll
    for (int pc = 0; pc < 2; pc++) {
        uint32_t st = sb + pc * STAGE;
        long kb = (long)pc * KC * 2;
        #pragma unroll
        for (int j = 0; j < 4; j++) {
            CP_ASYNC16(st + soff[j], aB + aoff[j] + kb);
            CP_ASYNC16(st + BUF_A + soff[j], bB + boff[j] + kb);
        }
        CP_COMMIT();
    }

    for (int c = 0; c < NC; c++) {
        // groups committed so far: g0..g_{c+1}; wait_group(1) => chunk c landed
        CP_WAIT(1);
        __syncthreads();

        uint32_t st = sb + (c % NSTG) * STAGE;
        #pragma unroll
        for (int kk = 0; kk < 4; kk++) {
            uint32_t kby = kk * 32;   // 16 halfs = 32B
            uint32_t ah[2][4], bh[2][4];
            #pragma unroll
            for (int mt = 0; mt < 2; mt++) {
                uint32_t ra = st + (wm + mt * 16) * ROWB + a_r + kby;
                LDSM_X4(ah[mt][0], ah[mt][1], ah[mt][2], ah[mt][3], ra);
            }
            #pragma unroll
            for (int np = 0; np < 2; np++) {
                uint32_t rb = st + BUF_A + (wn + np * 16) * ROWB + b_r + kby;
                LDSM_X4(bh[np][0], bh[np][1], bh[np][2], bh[np][3], rb);
            }
            #pragma unroll
            for (int mt = 0; mt < 2; mt++) {
                #pragma unroll
                for (int np = 0; np < 2; np++) {
                    #pragma unroll
                    for (int q = 0; q < 2; q++) {
                        MMA16816(acc[mt][np * 2 + q], ah[mt],
                                 bh[np][q * 2], bh[np][q * 2 + 1]);
                    }
                }
            }
        }

        // prefetch chunk c+2 into stage (c+2)%3 (free past this iter's barrier);
        // commit UNCONDITIONALLY to keep group accounting at the tail.
        if (c + 2 < NC) {
            uint32_t sn = sb + ((c + 2) % NSTG) * STAGE;
            long kb = (long)(c + 2) * KC * 2;
            #pragma unroll
            for (int j = 0; j < 4; j++) {
                CP_ASYNC16(sn + soff[j], aB + aoff[j] + kb);
                CP_ASYNC16(sn + BUF_A + soff[j], bB + boff[j] + kb);
            }
        }
        CP_COMMIT();
    }

    // epilogue: warp tile 32x32; thread rows wm+mt*16+(l>>2)+8rh, cols wn+nt*8+2(l&3)
    #pragma unroll
    for (int mt = 0; mt < 2; mt++) {
        #pragma unroll
        for (int nt = 0; nt < 4; nt++) {
            int row0 = m0 + wm + mt * 16 + (l >> 2);
            int col = n0 + wn + nt * 8 + ((l & 3) << 1);
            #pragma unroll
            for (int rh = 0; rh < 2; rh++) {
                int row = row0 + rh * 8;
                float d0 = acc[mt][nt][rh * 2 + 0];
                float d1 = acc[mt][nt][rh * 2 + 1];
                if (MODE == 0) {
                    float2 xv = *(const float2*)(x + (long)row * E_DIM + col);
                    float2 bv = *(const float2*)(bias + col);
                    float o0 = gelu_tanh(xv.x + d0 + bv.x);
                    float o1 = gelu_tanh(xv.y + d1 + bv.y);
                    *(__half2*)(outC + (long)row * ldc + coloff + col) =
                        __floats2half2_rn(o0, o1);
                } else {
                    float2 o;
                    o.x = d0; o.y = d1;
                    *(float2*)(outF + (long)row * ldc + col) = o;
                }
            }
        }
    }
}

// ---------------- reduce: out = x + GELU(sum_s part[s] + bm) ----------------
__global__ __launch_bounds__(256) void reduce_out(const float* __restrict__ part,
                                                  const float* __restrict__ x,
                                                  const float* __restrict__ bm,
                                                  float* __restrict__ out) {
    const long QT = (long)BS_TOT * E4;     // total float4 elements
    long i = (long)blockIdx.x * 256 + threadIdx.x;
    if (i >= QT) return;
    int colq = (int)(i % E4);
    const float4* p4 = (const float4*)part;
    float4 s = p4[i];
    #pragma unroll
    for (int sp = 1; sp < NSPLIT; sp++) {
        float4 t = p4[sp * QT + i];
        s.x += t.x; s.y += t.y; s.z += t.z; s.w += t.w;
    }
    float4 bv = ((const float4*)bm)[colq];
    float4 xv = ((const float4*)x)[i];
    float4 o;
    o.x = xv.x + gelu_tanh(s.x + bv.x);
    o.y = xv.y + gelu_tanh(s.y + bv.y);
    o.z = xv.z + gelu_tanh(s.z + bv.z);
    o.w = xv.w + gelu_tanh(s.w + bv.w);
    ((float4*)out)[i] = o;
}

// ---------------- launch ----------------
extern "C" void kernel_launch(void* const* d_in, const int* in_sizes, int n_in,
                              void* d_out, int out_size) {
    (void)in_sizes; (void)n_in; (void)out_size;
    const float* x     = (const float*)d_in[0];   // [2048,768]
    const float* y     = (const float*)d_in[1];   // [2048,36,768]
    const float* gamma = (const float*)d_in[2];   // [4,768]
    const float* beta  = (const float*)d_in[3];   // [4,768]
    const float* W1    = (const float*)d_in[4];   // [4,768,768]
    const float* b1    = (const float*)d_in[5];   // [4,768]
    // d_in[6] = W2x, d_in[8] = b2: cancel in the softmax — unused.
    const float* W2y   = (const float*)d_in[7];   // [4,768]
    const float* Wm    = (const float*)d_in[9];   // [3072,768]
    const float* bm    = (const float*)d_in[10];  // [768]
    float* out = (float*)d_out;

    __half *p_a, *p_w1t, *p_cat, *p_wmt;
    float* p_part;
    cudaGetSymbolAddress((void**)&p_a, g_a);
    cudaGetSymbolAddress((void**)&p_w1t, g_w1t);
    cudaGetSymbolAddress((void**)&p_cat, g_cat);
    cudaGetSymbolAddress((void**)&p_wmt, g_wmt);
    cudaGetSymbolAddress((void**)&p_part, g_part);

    cudaFuncSetAttribute(gemm_mma<0>, cudaFuncAttributeMaxDynamicSharedMemorySize, GEMM_SMEM);
    cudaFuncSetAttribute(gemm_mma<2>, cudaFuncAttributeMaxDynamicSharedMemorySize, GEMM_SMEM);

    prep_all<<<4992, 256>>>(W1, Wm, W2y, gamma, p_w1t, p_wmt);
    fused_y<<<BS_TOT, 256>>>(y, gamma, beta);

    // GEMM1 (per head): cat[:, h*768+n] = GELU(x + A_h @ W1[h]^T + b1[h])
    gemm_mma<0><<<dim3(E_DIM / TNV, BS_TOT / TMV, H_NUM), 128, GEMM_SMEM>>>(
        p_a, (long)BS_TOT * E_DIM, E_DIM,
        p_w1t, (long)E_DIM * E_DIM, E_DIM,
        b1, E_DIM, x,
        nullptr, p_cat, CATD, E_DIM, E_DIM);
    // GEMM2 split-K: part[s] = cat[:, s*768:(s+1)*768] @ WmT[:, s*768:(s+1)*768]^T
    gemm_mma<2><<<dim3(E_DIM / TNV, BS_TOT / TMV, NSPLIT), 128, GEMM_SMEM>>>(
        p_cat, 768, CATD,
        p_wmt, 768, CATD,
        bm, 0, nullptr,
        p_part, nullptr, E_DIM, BS_TOT * E_DIM, CATD / NSPLIT);
    // reduce: out = x + GELU(sum parts + bm)
    reduce_out<<<(BS_TOT * E4 + 255) / 256, 256>>>(p_part, x, bm, out);
}